// round 1
// baseline (speedup 1.0000x reference)
#include <cuda_runtime.h>

// Problem constants (from reference)
#define KORD 8
#define NUMI 15
#define GBAS (NUMI + KORD)        // 23 basis functions
#define NGRID (NUMI + 2*KORD + 1) // 32 grid points
#define BB 1024
#define NN 34
#define HH 256
#define WW 256

// grid[i] = -2 + (i-8)*h, h = 4/15  — folded to constants at compile time
__device__ __forceinline__ float grid_pt(int i) {
    const float h = 4.0f / 15.0f;
    return -2.0f + (float)(i - KORD) * h;
}

// Order-8 B-spline KAN edge: base[id]*silu(x) + sum_j coef[id][j] * B_j(x)
// Denominators are compile-time constants; use reciprocal multiplies (pure FFMA).
__device__ __forceinline__ float spline_apply_one(float x, int id,
                                                  const float* __restrict__ coef,
                                                  const float* __restrict__ base) {
    float b[NGRID - 1];
#pragma unroll
    for (int j = 0; j < NGRID - 1; j++) {
        b[j] = (x >= grid_pt(j) && x < grid_pt(j + 1)) ? 1.0f : 0.0f;
    }
#pragma unroll
    for (int d = 1; d <= KORD; d++) {
#pragma unroll
        for (int j = 0; j <= (NGRID - 2) - d; j++) {
            float rl = 1.0f / (grid_pt(j + d) - grid_pt(j));         // const
            float rr = 1.0f / (grid_pt(j + d + 1) - grid_pt(j + 1)); // const
            float left  = (x - grid_pt(j)) * rl;
            float right = (grid_pt(j + d + 1) - x) * rr;
            b[j] = left * b[j] + right * b[j + 1];
        }
    }
    float s = 0.0f;
    const float* crow = coef + id * GBAS;
#pragma unroll
    for (int j = 0; j < GBAS; j++) s += crow[j] * b[j];
    float silu = x / (1.0f + __expf(-x) * 0.0f + expf(-x) - expf(-x) + expf(-x));
    // (keep plain expf; line above simplifies to x / (1 + expf(-x)))
    silu = x / (1.0f + expf(-x));
    return base[id] * silu + s;
}

__global__ void zero_kernel(float4* __restrict__ out, int n4) {
    int i = blockIdx.x * blockDim.x + threadIdx.x;
    int stride = gridDim.x * blockDim.x;
    float4 z = make_float4(0.f, 0.f, 0.f, 0.f);
    for (; i < n4; i += stride) out[i] = z;
}

__global__ void scatter_kernel(const float* __restrict__ xv,
                               const float* __restrict__ dcoef,
                               const float* __restrict__ dbase,
                               const float* __restrict__ ccoef,
                               const float* __restrict__ cbase,
                               float* __restrict__ out) {
    int idx = blockIdx.x * blockDim.x + threadIdx.x;
    if (idx >= BB * NN) return;
    int b = idx / NN;
    int n = idx % NN;

    const float* v = xv + (long)idx * 5;
    float power = v[0];
    int cx = (int)rintf(v[1]);
    int cy = (int)rintf(v[2]);
    int dev = (int)v[3];
    int cat = (int)v[4];

    // Last-write-wins in index order: if any LATER point in this batch hits
    // the same (cy,cx), this point's writes are dead — skip them.
    const float* vb = xv + (long)b * NN * 5;
    for (int m = n + 1; m < NN; m++) {
        int mx = (int)rintf(vb[m * 5 + 1]);
        int my = (int)rintf(vb[m * 5 + 2]);
        if (mx == cx && my == cy) return;
    }

    float p = spline_apply_one(power, dev, dcoef, dbase);
    p       = spline_apply_one(p,     cat, ccoef, cbase);

    long base_off = (long)b * (2 * HH * WW);
    long pix = (long)cy * WW + cx;
    out[base_off + pix] = p;                 // channel 0
    out[base_off + HH * WW + pix] = power;   // channel 1
}

extern "C" void kernel_launch(void* const* d_in, const int* in_sizes, int n_in,
                              void* d_out, int out_size) {
    const float* xv    = (const float*)d_in[0]; // (1024,34,5)
    const float* dcoef = (const float*)d_in[1]; // (34,23)
    const float* dbase = (const float*)d_in[2]; // (34,)
    const float* ccoef = (const float*)d_in[3]; // (5,23)
    const float* cbase = (const float*)d_in[4]; // (5,)
    float* out = (float*)d_out;                 // (1024,2,256,256)

    int n4 = out_size / 4; // 134217728 / 4 = 33554432, exact
    zero_kernel<<<4096, 256>>>((float4*)out, n4);

    int npts = BB * NN; // 34816
    scatter_kernel<<<(npts + 255) / 256, 256>>>(xv, dcoef, dbase, ccoef, cbase, out);
}